// round 15
// baseline (speedup 1.0000x reference)
#include <cuda_runtime.h>
#include <math.h>

#define NL 10000
#define NP 100000
#define PL 8
#define HH 32
#define NROUNDS 8

// Scratch state (no allocations allowed)
__device__ __align__(256) float g_link_state[NL * HH];
__device__ __align__(256) float g_path_state[NP * HH];
__device__ __align__(256) float g_agg[NL * HH];
// Per-link input-side projection, biases folded.
// Layout per link (96 floats): [0:32) = Z_j ; [32:96) = interleaved (R_j, N_j) pairs.
__device__ __align__(256) float g_proj[NL * 96];

__device__ __forceinline__ float sigf(float v) { return 1.0f / (1.0f + expf(-v)); }

// Fast activations. __expf error ~2^-21 rel; far inside 1e-3 budget.
__device__ __forceinline__ float fsig(float v) {
    return __fdividef(1.0f, 1.0f + __expf(-v));
}
__device__ __forceinline__ float ftanh(float v) {
    float e = __expf(-2.0f * fabsf(v));
    float t = __fdividef(1.0f - e, 1.0f + e);
    return copysignf(t, v);
}

// Packed fp32x2 helpers (sm_100+). Bit-exact fp32 FMA semantics, 2 lanes/instr.
#define PACKF2(out, lo, hi) \
    asm("mov.b64 %0, {%1, %2};" : "=l"(out) : "r"(__float_as_uint(lo)), "r"(__float_as_uint(hi)))
#define UNPACKF2(lo, hi, in) \
    do { unsigned int _ul, _uh; \
         asm("mov.b64 {%0, %1}, %2;" : "=r"(_ul), "=r"(_uh) : "l"(in)); \
         lo = __uint_as_float(_ul); hi = __uint_as_float(_uh); } while (0)
#define FMAF2(d, a, b, c) \
    asm("fma.rn.f32x2 %0, %1, %2, %3;" : "=l"(d) : "l"(a), "l"(b), "l"(c))

// ---------------------------------------------------------------------------
// Init
// ---------------------------------------------------------------------------
__global__ void init_kernel(const float* __restrict__ cap, const float* __restrict__ bw) {
    int i = blockIdx.x * blockDim.x + threadIdx.x;
    if (i < NL * HH) {
        g_link_state[i] = ((i & 31) == 0) ? cap[i >> 5] : 0.0f;
        g_agg[i] = 0.0f;
    }
    if (i < NP * HH) {
        g_path_state[i] = ((i & 31) == 0) ? bw[i >> 5] : 0.0f;
    }
}

// ---------------------------------------------------------------------------
// Projection kernel: proj[link] = Wih @ link_state[link] with biases folded.
// One warp per link, lane j computes (Z_j, R_j, N_j).
// ---------------------------------------------------------------------------
#define NT_PROJ 256

__global__ void __launch_bounds__(NT_PROJ) proj_kernel(
    const float* __restrict__ Wih, const float* __restrict__ bih,
    const float* __restrict__ bhh)
{
    __shared__ float sWih[3072];
    __shared__ float sb[192];
    const int tid = threadIdx.x;
    for (int i = tid; i < 3072; i += NT_PROJ) sWih[i] = Wih[i];
    if (tid < 96) { sb[tid] = bih[tid]; sb[96 + tid] = bhh[tid]; }
    __syncthreads();

    const int gid = blockIdx.x * NT_PROJ + tid;
    const int link = gid >> 5;
    const int j = gid & 31;
    if (link >= NL) return;

    float x[32];
    {
        const float4* xp = (const float4*)(g_link_state + (size_t)link * 32);
#pragma unroll
        for (int k = 0; k < 8; k++) {
            float4 v = xp[k];
            x[4*k] = v.x; x[4*k+1] = v.y; x[4*k+2] = v.z; x[4*k+3] = v.w;
        }
    }

#define DOTX(ROW, OUT)                                                                  \
    do {                                                                                \
        const float4* wi_ = (const float4*)(sWih + (ROW) * 32);                         \
        float s0 = 0.f, s1 = 0.f, s2 = 0.f, s3 = 0.f;                                   \
        _Pragma("unroll")                                                               \
        for (int k_ = 0; k_ < 2; k_++) {                                                \
            float4 a = wi_[4*k_+0], b = wi_[4*k_+1], c = wi_[4*k_+2], d = wi_[4*k_+3];  \
            s0 = fmaf(a.x, x[16*k_+ 0], s0); s0 = fmaf(a.y, x[16*k_+ 1], s0);           \
            s0 = fmaf(a.z, x[16*k_+ 2], s0); s0 = fmaf(a.w, x[16*k_+ 3], s0);           \
            s1 = fmaf(b.x, x[16*k_+ 4], s1); s1 = fmaf(b.y, x[16*k_+ 5], s1);           \
            s1 = fmaf(b.z, x[16*k_+ 6], s1); s1 = fmaf(b.w, x[16*k_+ 7], s1);           \
            s2 = fmaf(c.x, x[16*k_+ 8], s2); s2 = fmaf(c.y, x[16*k_+ 9], s2);           \
            s2 = fmaf(c.z, x[16*k_+10], s2); s2 = fmaf(c.w, x[16*k_+11], s2);           \
            s3 = fmaf(d.x, x[16*k_+12], s3); s3 = fmaf(d.y, x[16*k_+13], s3);           \
            s3 = fmaf(d.z, x[16*k_+14], s3); s3 = fmaf(d.w, x[16*k_+15], s3);           \
        }                                                                               \
        OUT = (s0 + s1) + (s2 + s3);                                                    \
    } while (0)

    float dz, dr, dn;
    DOTX(32 + j, dz);
    DOTX(j, dr);
    DOTX(64 + j, dn);
#undef DOTX

    float* pp = g_proj + (size_t)link * 96;
    pp[j]             = dz + sb[32 + j] + sb[128 + j];
    pp[32 + 2*j]      = dr + sb[j] + sb[96 + j];
    pp[32 + 2*j + 1]  = dn + sb[64 + j];
}

// ---------------------------------------------------------------------------
// Path kernel (R15): R10 structure, but hop messages are BUFFERED IN REGISTERS
// (m0[8], m1[8], constant-indexed) and ALL atomics are issued in one burst at
// pair end — the hop loop's LSU stream is pure proj LDGs, so the serial
// dependency chain never queues behind atomic drains. Atomic bursts overlap
// the next pair's compute phase.
// ---------------------------------------------------------------------------
#define NT_PATH 192
#define PATH_BLOCKS 296

__global__ void __launch_bounds__(NT_PATH, 2) path_kernel(
    const int* __restrict__ links,
    const float* __restrict__ Whh, const float* __restrict__ bhh)
{
    __shared__ __align__(16) unsigned long long sA[2][NT_PATH / 2];  // path0 packed h
    __shared__ __align__(16) unsigned long long sB[2][NT_PATH / 2];  // path1 packed h

    const int lane = threadIdx.x & 31;
    const int wbase = threadIdx.x & ~31;
    const int warp_global = (blockIdx.x * (NT_PATH / 32)) + (threadIdx.x >> 5);
    const int n_warps = gridDim.x * (NT_PATH / 32);
    const int pslot = (wbase >> 1) + (lane >> 1);

    // Pre-packed weight pairs: Wz2[k] = (Wz[2k], Wz[2k+1]) etc.
    unsigned long long Wz2[16], Wr2[16], Wn2[16];
    {
        const float2* wz = (const float2*)(Whh + (size_t)(32 + lane) * 32);
        const float2* wr = (const float2*)(Whh + (size_t)lane * 32);
        const float2* wn = (const float2*)(Whh + (size_t)(64 + lane) * 32);
#pragma unroll
        for (int k = 0; k < 16; k++) {
            float2 a = wz[k]; PACKF2(Wz2[k], a.x, a.y);
            float2 b = wr[k]; PACKF2(Wr2[k], b.x, b.y);
            float2 c = wn[k]; PACKF2(Wn2[k], c.x, c.y);
        }
    }
    const float bn = bhh[64 + lane];

    for (int pi = warp_global; pi < NP / 2; pi += n_warps) {
        const int p0 = pi * 2;
        float h0 = g_path_state[(size_t)p0 * 32 + lane];
        float h1 = g_path_state[(size_t)p0 * 32 + 32 + lane];
        // lane<8: path0 hop ids; lane 8..15: path1 hop ids (contiguous in links)
        int links16 = (lane < 16) ? links[(size_t)p0 * 8 + lane] : 0;

        float m0[PL], m1[PL];   // per-hop messages, register-buffered

#pragma unroll
        for (int t = 0; t < PL; t++) {
            const int link0 = __shfl_sync(0xffffffffu, links16, t);
            const int link1 = __shfl_sync(0xffffffffu, links16, 8 + t);
            const float* pp0 = g_proj + (size_t)link0 * 96;
            const float* pp1 = g_proj + (size_t)link1 * 96;
            const float  Zp0 = pp0[lane];
            const float2 RN0 = *(const float2*)(pp0 + 32 + 2 * lane);
            const float  Zp1 = pp1[lane];
            const float2 RN1 = *(const float2*)(pp1 + 32 + 2 * lane);

            // Stage packed h pairs (even lanes store (h_j, h_{j+1}))
            const int par = t & 1;
            const float h0n = __shfl_down_sync(0xffffffffu, h0, 1);
            const float h1n = __shfl_down_sync(0xffffffffu, h1, 1);
            unsigned long long q0p, q1p;
            PACKF2(q0p, h0, h0n);
            PACKF2(q1p, h1, h1n);
            if (!(lane & 1)) { sA[par][pslot] = q0p; sB[par][pslot] = q1p; }
            __syncwarp();

            const ulonglong2* hv0 = (const ulonglong2*)&sA[par][wbase >> 1];
            const ulonglong2* hv1 = (const ulonglong2*)&sB[par][wbase >> 1];
            unsigned long long az0 = 0ull, ar0 = 0ull, an0 = 0ull;
            unsigned long long az1 = 0ull, ar1 = 0ull, an1 = 0ull;
#pragma unroll
            for (int kk = 0; kk < 8; kk++) {
                const ulonglong2 u0 = hv0[kk];   // broadcast LDS.128: 2 packed pairs
                const ulonglong2 u1 = hv1[kk];
                FMAF2(az0, Wz2[2*kk],   u0.x, az0);
                FMAF2(az0, Wz2[2*kk+1], u0.y, az0);
                FMAF2(ar0, Wr2[2*kk],   u0.x, ar0);
                FMAF2(ar0, Wr2[2*kk+1], u0.y, ar0);
                FMAF2(an0, Wn2[2*kk],   u0.x, an0);
                FMAF2(an0, Wn2[2*kk+1], u0.y, an0);
                FMAF2(az1, Wz2[2*kk],   u1.x, az1);
                FMAF2(az1, Wz2[2*kk+1], u1.y, az1);
                FMAF2(ar1, Wr2[2*kk],   u1.x, ar1);
                FMAF2(ar1, Wr2[2*kk+1], u1.y, ar1);
                FMAF2(an1, Wn2[2*kk],   u1.x, an1);
                FMAF2(an1, Wn2[2*kk+1], u1.y, an1);
            }

            {
                float al, ah, bl, bh, cl, ch;
                UNPACKF2(al, ah, az0);
                UNPACKF2(bl, bh, ar0);
                UNPACKF2(cl, ch, an0);
                const float z = fsig(Zp0 + (al + ah));
                const float r = fsig(RN0.x + (bl + bh));
                const float n = ftanh(RN0.y + r * ((cl + ch) + bn));
                h0 = fmaf(z, h0 - n, n);
                m0[t] = h0;                       // buffer message in regs
            }
            {
                float al, ah, bl, bh, cl, ch;
                UNPACKF2(al, ah, az1);
                UNPACKF2(bl, bh, ar1);
                UNPACKF2(cl, ch, an1);
                const float z = fsig(Zp1 + (al + ah));
                const float r = fsig(RN1.x + (bl + bh));
                const float n = ftanh(RN1.y + r * ((cl + ch) + bn));
                h1 = fmaf(z, h1 - n, n);
                m1[t] = h1;                       // buffer message in regs
            }
        }

        // ---- deferred atomic burst: fire-and-forget, overlaps next pair ----
#pragma unroll
        for (int t = 0; t < PL; t++) {
            const int link0 = __shfl_sync(0xffffffffu, links16, t);
            const int link1 = __shfl_sync(0xffffffffu, links16, 8 + t);
            atomicAdd(g_agg + (size_t)link0 * 32 + lane, m0[t]);
            atomicAdd(g_agg + (size_t)link1 * 32 + lane, m1[t]);
        }

        g_path_state[(size_t)p0 * 32 + lane] = h0;
        g_path_state[(size_t)p0 * 32 + 32 + lane] = h1;
    }
}

// ---------------------------------------------------------------------------
// Link kernel (exact R6 version — known good 26us): one GRU step per link.
// input x = agg, hidden h = link_state. Zeroes agg for the next round.
// ---------------------------------------------------------------------------
#define NT_LINK 64

#define DOT2(ROW_I, ROW_H, OUT_SI, OUT_SH)                                              \
    do {                                                                                \
        const float4* wi_ = (const float4*)(sWih + (ROW_I) * 32);                       \
        const float4* wh_ = (const float4*)(sWhh + (ROW_H) * 32);                       \
        float si0 = 0.f, si1 = 0.f, sh0 = 0.f, sh1 = 0.f;                               \
        _Pragma("unroll")                                                               \
        for (int k_ = 0; k_ < 8; k_ += 2) {                                             \
            float4 a = wi_[k_], b = wh_[k_], c = wi_[k_ + 1], d = wh_[k_ + 1];          \
            si0 = fmaf(a.x, x[4*k_+0], si0); si0 = fmaf(a.y, x[4*k_+1], si0);           \
            si0 = fmaf(a.z, x[4*k_+2], si0); si0 = fmaf(a.w, x[4*k_+3], si0);           \
            sh0 = fmaf(b.x, h[4*k_+0], sh0); sh0 = fmaf(b.y, h[4*k_+1], sh0);           \
            sh0 = fmaf(b.z, h[4*k_+2], sh0); sh0 = fmaf(b.w, h[4*k_+3], sh0);           \
            si1 = fmaf(c.x, x[4*k_+4], si1); si1 = fmaf(c.y, x[4*k_+5], si1);           \
            si1 = fmaf(c.z, x[4*k_+6], si1); si1 = fmaf(c.w, x[4*k_+7], si1);           \
            sh1 = fmaf(d.x, h[4*k_+4], sh1); sh1 = fmaf(d.y, h[4*k_+5], sh1);           \
            sh1 = fmaf(d.z, h[4*k_+6], sh1); sh1 = fmaf(d.w, h[4*k_+7], sh1);           \
        }                                                                               \
        OUT_SI = si0 + si1; OUT_SH = sh0 + sh1;                                         \
    } while (0)

__global__ void __launch_bounds__(NT_LINK) link_kernel(
    const float* __restrict__ Wih, const float* __restrict__ Whh,
    const float* __restrict__ bih, const float* __restrict__ bhh)
{
    __shared__ float sWih[3072];
    __shared__ float sWhh[3072];
    __shared__ float sb[192];
    __shared__ float sZ[32 * NT_LINK];
    __shared__ float sN[32 * NT_LINK];

    const int tid = threadIdx.x;
    for (int i = tid; i < 3072; i += NT_LINK) { sWih[i] = Wih[i]; sWhh[i] = Whh[i]; }
    for (int i = tid; i < 96; i += NT_LINK) { sb[i] = bih[i]; sb[96 + i] = bhh[i]; }
    __syncthreads();

    const int l = blockIdx.x * NT_LINK + tid;
    if (l >= NL) return;

    float h[32], x[32];
    {
        const float4* hp = (const float4*)(g_link_state + (size_t)l * 32);
        const float4* xp = (const float4*)(g_agg + (size_t)l * 32);
#pragma unroll
        for (int k = 0; k < 8; k++) {
            float4 v = hp[k];
            h[4*k] = v.x; h[4*k+1] = v.y; h[4*k+2] = v.z; h[4*k+3] = v.w;
            float4 u = xp[k];
            x[4*k] = u.x; x[4*k+1] = u.y; x[4*k+2] = u.z; x[4*k+3] = u.w;
        }
    }

    for (int j = 0; j < 32; j++) {
        float si, sh;
        DOT2(32 + j, 32 + j, si, sh);
        sZ[j * NT_LINK + tid] = sigf(si + sb[32 + j] + sh + sb[128 + j]);
    }
    for (int j = 0; j < 32; j++) {
        float sir, shr;
        DOT2(j, j, sir, shr);
        float r = sigf(sir + sb[j] + shr + sb[96 + j]);
        float sin_, shn;
        DOT2(64 + j, 64 + j, sin_, shn);
        float n = tanhf(sin_ + sb[64 + j] + r * (shn + sb[160 + j]));
        sN[j * NT_LINK + tid] = n;
    }

    float4* hp = (float4*)(g_link_state + (size_t)l * 32);
    float4* ap = (float4*)(g_agg + (size_t)l * 32);
#pragma unroll
    for (int k = 0; k < 8; k++) {
        float4 v;
        {
            int j = 4 * k;
            float z0 = sZ[(j+0) * NT_LINK + tid], n0 = sN[(j+0) * NT_LINK + tid];
            float z1 = sZ[(j+1) * NT_LINK + tid], n1 = sN[(j+1) * NT_LINK + tid];
            float z2 = sZ[(j+2) * NT_LINK + tid], n2 = sN[(j+2) * NT_LINK + tid];
            float z3 = sZ[(j+3) * NT_LINK + tid], n3 = sN[(j+3) * NT_LINK + tid];
            v.x = fmaf(z0, h[j+0] - n0, n0);
            v.y = fmaf(z1, h[j+1] - n1, n1);
            v.z = fmaf(z2, h[j+2] - n2, n2);
            v.w = fmaf(z3, h[j+3] - n3, n3);
        }
        hp[k] = v;
        ap[k] = make_float4(0.f, 0.f, 0.f, 0.f);  // clear agg for next round
    }
}

// ---------------------------------------------------------------------------
// Readout MLP: 32 -> relu 8 -> relu 8 -> 1
// ---------------------------------------------------------------------------
__global__ void __launch_bounds__(128) readout_kernel(
    const float* __restrict__ W1, const float* __restrict__ b1,
    const float* __restrict__ W2, const float* __restrict__ b2,
    const float* __restrict__ W3, const float* __restrict__ b3,
    float* __restrict__ out)
{
    __shared__ float sW1[256], sW2[64], sW3[8], sb1[8], sb2[8], sb3;
    int tid = threadIdx.x;
    for (int i = tid; i < 256; i += 128) sW1[i] = W1[i];
    if (tid < 64) sW2[tid] = W2[tid];
    if (tid < 8) { sW3[tid] = W3[tid]; sb1[tid] = b1[tid]; sb2[tid] = b2[tid]; }
    if (tid == 0) sb3 = b3[0];
    __syncthreads();

    int p = blockIdx.x * 128 + tid;
    if (p >= NP) return;

    float x[32];
    const float4* hp = (const float4*)(g_path_state + (size_t)p * 32);
#pragma unroll
    for (int k = 0; k < 8; k++) {
        float4 v = hp[k];
        x[4*k] = v.x; x[4*k+1] = v.y; x[4*k+2] = v.z; x[4*k+3] = v.w;
    }
    float y[8];
#pragma unroll
    for (int j = 0; j < 8; j++) {
        float s = sb1[j];
#pragma unroll
        for (int k = 0; k < 32; k++) s = fmaf(sW1[j * 32 + k], x[k], s);
        y[j] = fmaxf(s, 0.0f);
    }
    float y2[8];
#pragma unroll
    for (int j = 0; j < 8; j++) {
        float s = sb2[j];
#pragma unroll
        for (int k = 0; k < 8; k++) s = fmaf(sW2[j * 8 + k], y[k], s);
        y2[j] = fmaxf(s, 0.0f);
    }
    float s = sb3;
#pragma unroll
    for (int k = 0; k < 8; k++) s = fmaf(sW3[k], y2[k], s);
    out[p] = s;
}

// ---------------------------------------------------------------------------
extern "C" void kernel_launch(void* const* d_in, const int* in_sizes, int n_in,
                              void* d_out, int out_size)
{
    const int*   links = (const int*)d_in[0];
    // d_in[1]=paths, d_in[2]=seqs: layout is paths=repeat, seqs=tile -> hop(p,t)=links[8p+t]
    const float* cap   = (const float*)d_in[3];
    const float* bw    = (const float*)d_in[4];
    const float* pWih  = (const float*)d_in[5];
    const float* pWhh  = (const float*)d_in[6];
    const float* pbih  = (const float*)d_in[7];
    const float* pbhh  = (const float*)d_in[8];
    const float* lWih  = (const float*)d_in[9];
    const float* lWhh  = (const float*)d_in[10];
    const float* lbih  = (const float*)d_in[11];
    const float* lbhh  = (const float*)d_in[12];
    const float* W1    = (const float*)d_in[13];
    const float* b1    = (const float*)d_in[14];
    const float* W2    = (const float*)d_in[15];
    const float* b2    = (const float*)d_in[16];
    const float* W3    = (const float*)d_in[17];
    const float* b3    = (const float*)d_in[18];
    float* out = (float*)d_out;

    init_kernel<<<(NP * HH + 255) / 256, 256>>>(cap, bw);

    const int link_blocks = (NL + NT_LINK - 1) / NT_LINK;
    const int proj_blocks = (NL * 32 + NT_PROJ - 1) / NT_PROJ;
    for (int r = 0; r < NROUNDS; r++) {
        proj_kernel<<<proj_blocks, NT_PROJ>>>(pWih, pbih, pbhh);
        path_kernel<<<PATH_BLOCKS, NT_PATH>>>(links, pWhh, pbhh);
        if (r < NROUNDS - 1)  // final link update is dead code (readout uses path_state)
            link_kernel<<<link_blocks, NT_LINK>>>(lWih, lWhh, lbih, lbhh);
    }
    readout_kernel<<<(NP + 127) / 128, 128>>>(W1, b1, W2, b2, W3, b3, out);
}

// round 16
// speedup vs baseline: 1.7750x; 1.7750x over previous
#include <cuda_runtime.h>
#include <math.h>

#define NL 10000
#define NP 100000
#define PL 8
#define HH 32
#define NROUNDS 8

// Scratch state (no allocations allowed)
__device__ __align__(256) float g_link_state[NL * HH];
__device__ __align__(256) float g_path_state[NP * HH];
__device__ __align__(256) float g_agg[NL * HH];
// Per-link input-side projection, biases folded.
// Layout per link (96 floats): [0:32) = Z_j ; [32:96) = interleaved (R_j, N_j) pairs.
__device__ __align__(256) float g_proj[NL * 96];

__device__ __forceinline__ float sigf(float v) { return 1.0f / (1.0f + expf(-v)); }

// HW tanh (sm_75+): single MUFU op, lat 16. abs err ~1e-4 worst case —
// far inside the 1e-3 budget (current margin 3.3e-7).
__device__ __forceinline__ float ftanh_hw(float v) {
    float r;
    asm("tanh.approx.f32 %0, %1;" : "=f"(r) : "f"(v));
    return r;
}
// sigmoid(x) = 0.5 + 0.5*tanh(x/2): 1 MUFU + 2 FMA (vs EX2+RCP chains).
__device__ __forceinline__ float fsig_hw(float v) {
    return fmaf(0.5f, ftanh_hw(0.5f * v), 0.5f);
}

// Packed fp32x2 helpers (sm_100+). Bit-exact fp32 FMA semantics, 2 lanes/instr.
#define PACKF2(out, lo, hi) \
    asm("mov.b64 %0, {%1, %2};" : "=l"(out) : "r"(__float_as_uint(lo)), "r"(__float_as_uint(hi)))
#define UNPACKF2(lo, hi, in) \
    do { unsigned int _ul, _uh; \
         asm("mov.b64 {%0, %1}, %2;" : "=r"(_ul), "=r"(_uh) : "l"(in)); \
         lo = __uint_as_float(_ul); hi = __uint_as_float(_uh); } while (0)
#define FMAF2(d, a, b, c) \
    asm("fma.rn.f32x2 %0, %1, %2, %3;" : "=l"(d) : "l"(a), "l"(b), "l"(c))

// ---------------------------------------------------------------------------
// Init
// ---------------------------------------------------------------------------
__global__ void init_kernel(const float* __restrict__ cap, const float* __restrict__ bw) {
    int i = blockIdx.x * blockDim.x + threadIdx.x;
    if (i < NL * HH) {
        g_link_state[i] = ((i & 31) == 0) ? cap[i >> 5] : 0.0f;
        g_agg[i] = 0.0f;
    }
    if (i < NP * HH) {
        g_path_state[i] = ((i & 31) == 0) ? bw[i >> 5] : 0.0f;
    }
}

// ---------------------------------------------------------------------------
// Projection kernel: proj[link] = Wih @ link_state[link] with biases folded.
// One warp per link, lane j computes (Z_j, R_j, N_j).
// ---------------------------------------------------------------------------
#define NT_PROJ 256

__global__ void __launch_bounds__(NT_PROJ) proj_kernel(
    const float* __restrict__ Wih, const float* __restrict__ bih,
    const float* __restrict__ bhh)
{
    __shared__ float sWih[3072];
    __shared__ float sb[192];
    const int tid = threadIdx.x;
    for (int i = tid; i < 3072; i += NT_PROJ) sWih[i] = Wih[i];
    if (tid < 96) { sb[tid] = bih[tid]; sb[96 + tid] = bhh[tid]; }
    __syncthreads();

    const int gid = blockIdx.x * NT_PROJ + tid;
    const int link = gid >> 5;
    const int j = gid & 31;
    if (link >= NL) return;

    float x[32];
    {
        const float4* xp = (const float4*)(g_link_state + (size_t)link * 32);
#pragma unroll
        for (int k = 0; k < 8; k++) {
            float4 v = xp[k];
            x[4*k] = v.x; x[4*k+1] = v.y; x[4*k+2] = v.z; x[4*k+3] = v.w;
        }
    }

#define DOTX(ROW, OUT)                                                                  \
    do {                                                                                \
        const float4* wi_ = (const float4*)(sWih + (ROW) * 32);                         \
        float s0 = 0.f, s1 = 0.f, s2 = 0.f, s3 = 0.f;                                   \
        _Pragma("unroll")                                                               \
        for (int k_ = 0; k_ < 2; k_++) {                                                \
            float4 a = wi_[4*k_+0], b = wi_[4*k_+1], c = wi_[4*k_+2], d = wi_[4*k_+3];  \
            s0 = fmaf(a.x, x[16*k_+ 0], s0); s0 = fmaf(a.y, x[16*k_+ 1], s0);           \
            s0 = fmaf(a.z, x[16*k_+ 2], s0); s0 = fmaf(a.w, x[16*k_+ 3], s0);           \
            s1 = fmaf(b.x, x[16*k_+ 4], s1); s1 = fmaf(b.y, x[16*k_+ 5], s1);           \
            s1 = fmaf(b.z, x[16*k_+ 6], s1); s1 = fmaf(b.w, x[16*k_+ 7], s1);           \
            s2 = fmaf(c.x, x[16*k_+ 8], s2); s2 = fmaf(c.y, x[16*k_+ 9], s2);           \
            s2 = fmaf(c.z, x[16*k_+10], s2); s2 = fmaf(c.w, x[16*k_+11], s2);           \
            s3 = fmaf(d.x, x[16*k_+12], s3); s3 = fmaf(d.y, x[16*k_+13], s3);           \
            s3 = fmaf(d.z, x[16*k_+14], s3); s3 = fmaf(d.w, x[16*k_+15], s3);           \
        }                                                                               \
        OUT = (s0 + s1) + (s2 + s3);                                                    \
    } while (0)

    float dz, dr, dn;
    DOTX(32 + j, dz);
    DOTX(j, dr);
    DOTX(64 + j, dn);
#undef DOTX

    float* pp = g_proj + (size_t)link * 96;
    pp[j]             = dz + sb[32 + j] + sb[128 + j];
    pp[32 + 2*j]      = dr + sb[j] + sb[96 + j];
    pp[32 + 2*j + 1]  = dn + sb[64 + j];
}

// ---------------------------------------------------------------------------
// Path kernel (R16 = exact R10 structure, activations -> HW tanh):
// 2 paths per warp, lane = feature; shared staging + packed FMA2 dots.
// Per hop-path: 3 MUFU (tanh.approx) instead of 6 MUFU + 2 RCP chains —
// shortens the hop-serial activation chain by ~60-80 cycles.
// ---------------------------------------------------------------------------
#define NT_PATH 192
#define PATH_BLOCKS 296

__global__ void __launch_bounds__(NT_PATH, 2) path_kernel(
    const int* __restrict__ links,
    const float* __restrict__ Whh, const float* __restrict__ bhh)
{
    __shared__ __align__(16) unsigned long long sA[2][NT_PATH / 2];  // path0 packed h
    __shared__ __align__(16) unsigned long long sB[2][NT_PATH / 2];  // path1 packed h

    const int lane = threadIdx.x & 31;
    const int wbase = threadIdx.x & ~31;
    const int warp_global = (blockIdx.x * (NT_PATH / 32)) + (threadIdx.x >> 5);
    const int n_warps = gridDim.x * (NT_PATH / 32);
    const int pslot = (wbase >> 1) + (lane >> 1);

    // Pre-packed weight pairs: Wz2[k] = (Wz[2k], Wz[2k+1]) etc.
    unsigned long long Wz2[16], Wr2[16], Wn2[16];
    {
        const float2* wz = (const float2*)(Whh + (size_t)(32 + lane) * 32);
        const float2* wr = (const float2*)(Whh + (size_t)lane * 32);
        const float2* wn = (const float2*)(Whh + (size_t)(64 + lane) * 32);
#pragma unroll
        for (int k = 0; k < 16; k++) {
            float2 a = wz[k]; PACKF2(Wz2[k], a.x, a.y);
            float2 b = wr[k]; PACKF2(Wr2[k], b.x, b.y);
            float2 c = wn[k]; PACKF2(Wn2[k], c.x, c.y);
        }
    }
    const float bn = bhh[64 + lane];

    for (int pi = warp_global; pi < NP / 2; pi += n_warps) {
        const int p0 = pi * 2;
        float h0 = g_path_state[(size_t)p0 * 32 + lane];
        float h1 = g_path_state[(size_t)p0 * 32 + 32 + lane];
        // lane<8: path0 hop ids; lane 8..15: path1 hop ids (contiguous in links)
        int links16 = (lane < 16) ? links[(size_t)p0 * 8 + lane] : 0;

#pragma unroll
        for (int t = 0; t < PL; t++) {
            const int link0 = __shfl_sync(0xffffffffu, links16, t);
            const int link1 = __shfl_sync(0xffffffffu, links16, 8 + t);
            const float* pp0 = g_proj + (size_t)link0 * 96;
            const float* pp1 = g_proj + (size_t)link1 * 96;
            const float  Zp0 = pp0[lane];
            const float2 RN0 = *(const float2*)(pp0 + 32 + 2 * lane);
            const float  Zp1 = pp1[lane];
            const float2 RN1 = *(const float2*)(pp1 + 32 + 2 * lane);

            // Stage packed h pairs (even lanes store (h_j, h_{j+1}))
            const int par = t & 1;
            const float h0n = __shfl_down_sync(0xffffffffu, h0, 1);
            const float h1n = __shfl_down_sync(0xffffffffu, h1, 1);
            unsigned long long q0p, q1p;
            PACKF2(q0p, h0, h0n);
            PACKF2(q1p, h1, h1n);
            if (!(lane & 1)) { sA[par][pslot] = q0p; sB[par][pslot] = q1p; }
            __syncwarp();

            const ulonglong2* hv0 = (const ulonglong2*)&sA[par][wbase >> 1];
            const ulonglong2* hv1 = (const ulonglong2*)&sB[par][wbase >> 1];
            unsigned long long az0 = 0ull, ar0 = 0ull, an0 = 0ull;
            unsigned long long az1 = 0ull, ar1 = 0ull, an1 = 0ull;
#pragma unroll
            for (int kk = 0; kk < 8; kk++) {
                const ulonglong2 u0 = hv0[kk];   // broadcast LDS.128: 2 packed pairs
                const ulonglong2 u1 = hv1[kk];
                FMAF2(az0, Wz2[2*kk],   u0.x, az0);
                FMAF2(az0, Wz2[2*kk+1], u0.y, az0);
                FMAF2(ar0, Wr2[2*kk],   u0.x, ar0);
                FMAF2(ar0, Wr2[2*kk+1], u0.y, ar0);
                FMAF2(an0, Wn2[2*kk],   u0.x, an0);
                FMAF2(an0, Wn2[2*kk+1], u0.y, an0);
                FMAF2(az1, Wz2[2*kk],   u1.x, az1);
                FMAF2(az1, Wz2[2*kk+1], u1.y, az1);
                FMAF2(ar1, Wr2[2*kk],   u1.x, ar1);
                FMAF2(ar1, Wr2[2*kk+1], u1.y, ar1);
                FMAF2(an1, Wn2[2*kk],   u1.x, an1);
                FMAF2(an1, Wn2[2*kk+1], u1.y, an1);
            }

            {
                float al, ah, bl, bh, cl, ch;
                UNPACKF2(al, ah, az0);
                UNPACKF2(bl, bh, ar0);
                UNPACKF2(cl, ch, an0);
                const float z = fsig_hw(Zp0 + (al + ah));
                const float r = fsig_hw(RN0.x + (bl + bh));
                const float n = ftanh_hw(RN0.y + r * ((cl + ch) + bn));
                h0 = fmaf(z, h0 - n, n);
                atomicAdd(g_agg + (size_t)link0 * 32 + lane, h0);
            }
            {
                float al, ah, bl, bh, cl, ch;
                UNPACKF2(al, ah, az1);
                UNPACKF2(bl, bh, ar1);
                UNPACKF2(cl, ch, an1);
                const float z = fsig_hw(Zp1 + (al + ah));
                const float r = fsig_hw(RN1.x + (bl + bh));
                const float n = ftanh_hw(RN1.y + r * ((cl + ch) + bn));
                h1 = fmaf(z, h1 - n, n);
                atomicAdd(g_agg + (size_t)link1 * 32 + lane, h1);
            }
        }

        g_path_state[(size_t)p0 * 32 + lane] = h0;
        g_path_state[(size_t)p0 * 32 + 32 + lane] = h1;
    }
}

// ---------------------------------------------------------------------------
// Link kernel (exact R6 version — known good 26us): one GRU step per link.
// input x = agg, hidden h = link_state. Zeroes agg for the next round.
// ---------------------------------------------------------------------------
#define NT_LINK 64

#define DOT2(ROW_I, ROW_H, OUT_SI, OUT_SH)                                              \
    do {                                                                                \
        const float4* wi_ = (const float4*)(sWih + (ROW_I) * 32);                       \
        const float4* wh_ = (const float4*)(sWhh + (ROW_H) * 32);                       \
        float si0 = 0.f, si1 = 0.f, sh0 = 0.f, sh1 = 0.f;                               \
        _Pragma("unroll")                                                               \
        for (int k_ = 0; k_ < 8; k_ += 2) {                                             \
            float4 a = wi_[k_], b = wh_[k_], c = wi_[k_ + 1], d = wh_[k_ + 1];          \
            si0 = fmaf(a.x, x[4*k_+0], si0); si0 = fmaf(a.y, x[4*k_+1], si0);           \
            si0 = fmaf(a.z, x[4*k_+2], si0); si0 = fmaf(a.w, x[4*k_+3], si0);           \
            sh0 = fmaf(b.x, h[4*k_+0], sh0); sh0 = fmaf(b.y, h[4*k_+1], sh0);           \
            sh0 = fmaf(b.z, h[4*k_+2], sh0); sh0 = fmaf(b.w, h[4*k_+3], sh0);           \
            si1 = fmaf(c.x, x[4*k_+4], si1); si1 = fmaf(c.y, x[4*k_+5], si1);           \
            si1 = fmaf(c.z, x[4*k_+6], si1); si1 = fmaf(c.w, x[4*k_+7], si1);           \
            sh1 = fmaf(d.x, h[4*k_+4], sh1); sh1 = fmaf(d.y, h[4*k_+5], sh1);           \
            sh1 = fmaf(d.z, h[4*k_+6], sh1); sh1 = fmaf(d.w, h[4*k_+7], sh1);           \
        }                                                                               \
        OUT_SI = si0 + si1; OUT_SH = sh0 + sh1;                                         \
    } while (0)

__global__ void __launch_bounds__(NT_LINK) link_kernel(
    const float* __restrict__ Wih, const float* __restrict__ Whh,
    const float* __restrict__ bih, const float* __restrict__ bhh)
{
    __shared__ float sWih[3072];
    __shared__ float sWhh[3072];
    __shared__ float sb[192];
    __shared__ float sZ[32 * NT_LINK];
    __shared__ float sN[32 * NT_LINK];

    const int tid = threadIdx.x;
    for (int i = tid; i < 3072; i += NT_LINK) { sWih[i] = Wih[i]; sWhh[i] = Whh[i]; }
    for (int i = tid; i < 96; i += NT_LINK) { sb[i] = bih[i]; sb[96 + i] = bhh[i]; }
    __syncthreads();

    const int l = blockIdx.x * NT_LINK + tid;
    if (l >= NL) return;

    float h[32], x[32];
    {
        const float4* hp = (const float4*)(g_link_state + (size_t)l * 32);
        const float4* xp = (const float4*)(g_agg + (size_t)l * 32);
#pragma unroll
        for (int k = 0; k < 8; k++) {
            float4 v = hp[k];
            h[4*k] = v.x; h[4*k+1] = v.y; h[4*k+2] = v.z; h[4*k+3] = v.w;
            float4 u = xp[k];
            x[4*k] = u.x; x[4*k+1] = u.y; x[4*k+2] = u.z; x[4*k+3] = u.w;
        }
    }

    for (int j = 0; j < 32; j++) {
        float si, sh;
        DOT2(32 + j, 32 + j, si, sh);
        sZ[j * NT_LINK + tid] = sigf(si + sb[32 + j] + sh + sb[128 + j]);
    }
    for (int j = 0; j < 32; j++) {
        float sir, shr;
        DOT2(j, j, sir, shr);
        float r = sigf(sir + sb[j] + shr + sb[96 + j]);
        float sin_, shn;
        DOT2(64 + j, 64 + j, sin_, shn);
        float n = tanhf(sin_ + sb[64 + j] + r * (shn + sb[160 + j]));
        sN[j * NT_LINK + tid] = n;
    }

    float4* hp = (float4*)(g_link_state + (size_t)l * 32);
    float4* ap = (float4*)(g_agg + (size_t)l * 32);
#pragma unroll
    for (int k = 0; k < 8; k++) {
        float4 v;
        {
            int j = 4 * k;
            float z0 = sZ[(j+0) * NT_LINK + tid], n0 = sN[(j+0) * NT_LINK + tid];
            float z1 = sZ[(j+1) * NT_LINK + tid], n1 = sN[(j+1) * NT_LINK + tid];
            float z2 = sZ[(j+2) * NT_LINK + tid], n2 = sN[(j+2) * NT_LINK + tid];
            float z3 = sZ[(j+3) * NT_LINK + tid], n3 = sN[(j+3) * NT_LINK + tid];
            v.x = fmaf(z0, h[j+0] - n0, n0);
            v.y = fmaf(z1, h[j+1] - n1, n1);
            v.z = fmaf(z2, h[j+2] - n2, n2);
            v.w = fmaf(z3, h[j+3] - n3, n3);
        }
        hp[k] = v;
        ap[k] = make_float4(0.f, 0.f, 0.f, 0.f);  // clear agg for next round
    }
}

// ---------------------------------------------------------------------------
// Readout MLP: 32 -> relu 8 -> relu 8 -> 1
// ---------------------------------------------------------------------------
__global__ void __launch_bounds__(128) readout_kernel(
    const float* __restrict__ W1, const float* __restrict__ b1,
    const float* __restrict__ W2, const float* __restrict__ b2,
    const float* __restrict__ W3, const float* __restrict__ b3,
    float* __restrict__ out)
{
    __shared__ float sW1[256], sW2[64], sW3[8], sb1[8], sb2[8], sb3;
    int tid = threadIdx.x;
    for (int i = tid; i < 256; i += 128) sW1[i] = W1[i];
    if (tid < 64) sW2[tid] = W2[tid];
    if (tid < 8) { sW3[tid] = W3[tid]; sb1[tid] = b1[tid]; sb2[tid] = b2[tid]; }
    if (tid == 0) sb3 = b3[0];
    __syncthreads();

    int p = blockIdx.x * 128 + tid;
    if (p >= NP) return;

    float x[32];
    const float4* hp = (const float4*)(g_path_state + (size_t)p * 32);
#pragma unroll
    for (int k = 0; k < 8; k++) {
        float4 v = hp[k];
        x[4*k] = v.x; x[4*k+1] = v.y; x[4*k+2] = v.z; x[4*k+3] = v.w;
    }
    float y[8];
#pragma unroll
    for (int j = 0; j < 8; j++) {
        float s = sb1[j];
#pragma unroll
        for (int k = 0; k < 32; k++) s = fmaf(sW1[j * 32 + k], x[k], s);
        y[j] = fmaxf(s, 0.0f);
    }
    float y2[8];
#pragma unroll
    for (int j = 0; j < 8; j++) {
        float s = sb2[j];
#pragma unroll
        for (int k = 0; k < 8; k++) s = fmaf(sW2[j * 8 + k], y[k], s);
        y2[j] = fmaxf(s, 0.0f);
    }
    float s = sb3;
#pragma unroll
    for (int k = 0; k < 8; k++) s = fmaf(sW3[k], y2[k], s);
    out[p] = s;
}

// ---------------------------------------------------------------------------
extern "C" void kernel_launch(void* const* d_in, const int* in_sizes, int n_in,
                              void* d_out, int out_size)
{
    const int*   links = (const int*)d_in[0];
    // d_in[1]=paths, d_in[2]=seqs: layout is paths=repeat, seqs=tile -> hop(p,t)=links[8p+t]
    const float* cap   = (const float*)d_in[3];
    const float* bw    = (const float*)d_in[4];
    const float* pWih  = (const float*)d_in[5];
    const float* pWhh  = (const float*)d_in[6];
    const float* pbih  = (const float*)d_in[7];
    const float* pbhh  = (const float*)d_in[8];
    const float* lWih  = (const float*)d_in[9];
    const float* lWhh  = (const float*)d_in[10];
    const float* lbih  = (const float*)d_in[11];
    const float* lbhh  = (const float*)d_in[12];
    const float* W1    = (const float*)d_in[13];
    const float* b1    = (const float*)d_in[14];
    const float* W2    = (const float*)d_in[15];
    const float* b2    = (const float*)d_in[16];
    const float* W3    = (const float*)d_in[17];
    const float* b3    = (const float*)d_in[18];
    float* out = (float*)d_out;

    init_kernel<<<(NP * HH + 255) / 256, 256>>>(cap, bw);

    const int link_blocks = (NL + NT_LINK - 1) / NT_LINK;
    const int proj_blocks = (NL * 32 + NT_PROJ - 1) / NT_PROJ;
    for (int r = 0; r < NROUNDS; r++) {
        proj_kernel<<<proj_blocks, NT_PROJ>>>(pWih, pbih, pbhh);
        path_kernel<<<PATH_BLOCKS, NT_PATH>>>(links, pWhh, pbhh);
        if (r < NROUNDS - 1)  // final link update is dead code (readout uses path_state)
            link_kernel<<<link_blocks, NT_LINK>>>(lWih, lWhh, lbih, lbhh);
    }
    readout_kernel<<<(NP + 127) / 128, 128>>>(W1, b1, W2, b2, W3, b3, out);
}